// round 3
// baseline (speedup 1.0000x reference)
#include <cuda_runtime.h>
#include <cstdint>
#include <math.h>

typedef unsigned long long ull;

#define BB 4096
#define LL 50
#define DD 64

constexpr int NTASK    = BB * 7;     // 6 tasks of 8 rows + 1 task of 2 rows per b
constexpr int THREADS1 = 512;
constexpr int NWARP    = 16;

// ---- smem layout (float offsets) ----
constexpr int O_W1Q = 0;              // gv_w1 (pt half only, K=64) quads -> 4096
constexpr int O_W2Q = 4096;           // gv_w2  -> 4096
constexpr int O_W3Q = 8192;           // gv_w3  -> 4096
constexpr int O_A1Q = 12288;          // att_w1 full K=128 -> 8192
constexpr int O_A2Q = 20480;          // att_w2 -> 4096
constexpr int O_W3V = 24576;          // att_w3 (64)
constexpr int O_BG1 = 24640;
constexpr int O_BG2 = 24704;
constexpr int O_BG3 = 24768;
constexpr int O_BA1 = 24832;
constexpr int O_BA2 = 24896;
constexpr int O_BA3 = 24960;          // 1 (padded to 64)
constexpr int O_EP  = 25024;          // er_proj[5][64] = 320
constexpr int O_XA  = 25344;          // 16 warps * 8 rows * 64
constexpr int O_XB  = O_XA + NWARP * 8 * 64;
constexpr int SMEM_FLOATS = O_XB + NWARP * 8 * 64;
constexpr int SMEM_BYTES  = SMEM_FLOATS * 4;   // 166912 B

// scratch (device-global, allowed per rules)
__device__ float g_scores[BB * LL];
__device__ float g_fjt[BB * LL * DD];

// ---- packed f32x2 helpers ----
__device__ __forceinline__ ull fma2(ull a, ull b, ull c) {
    ull d;
    asm("fma.rn.f32x2 %0, %1, %2, %3;" : "=l"(d) : "l"(a), "l"(b), "l"(c));
    return d;
}
__device__ __forceinline__ float2 unpack2(ull v) {
    float2 f;
    asm("mov.b64 {%0, %1}, %2;" : "=f"(f.x), "=f"(f.y) : "l"(v));
    return f;
}
__device__ __forceinline__ ull pack2(float x, float y) {
    ull v;
    asm("mov.b64 %0, {%1, %2};" : "=l"(v) : "f"(x), "f"(y));
    return v;
}

// Accumulating GEMV over R rows; lane computes output channels (lane, lane+32)
// as f32x2 (even-k, odd-k) partial pairs. Caller pre-initializes accA/accB.
// Wq layout per entry e = k2*32+jj : (w[2k2][jj], w[2k2+1][jj], w[2k2][jj+32], w[2k2+1][jj+32])
template<int R, int K, int XS>
__device__ __forceinline__ void gemm_acc(
    const float* __restrict__ xs, const ulonglong2* __restrict__ Wq,
    ull* accA, ull* accB, int lane)
{
#pragma unroll 4
    for (int k4 = 0; k4 < K / 4; k4++) {
        ulonglong2 w0 = Wq[(2 * k4) * 32 + lane];
        ulonglong2 w1 = Wq[(2 * k4 + 1) * 32 + lane];
#pragma unroll
        for (int r = 0; r < R; r++) {
            ulonglong2 xv = *reinterpret_cast<const ulonglong2*>(xs + r * XS + 4 * k4);
            accA[r] = fma2(xv.x, w0.x, accA[r]);
            accB[r] = fma2(xv.x, w0.y, accB[r]);
            accA[r] = fma2(xv.y, w1.x, accA[r]);
            accB[r] = fma2(xv.y, w1.y, accB[r]);
        }
    }
}

__device__ __forceinline__ void load_quads(float* dstf, const float* __restrict__ w, int K, int tid) {
    float4* dst = reinterpret_cast<float4*>(dstf);
    int n = (K / 2) * 32;
    for (int e = tid; e < n; e += THREADS1) {
        int k2 = e >> 5, jj = e & 31;
        const float* p = w + (2 * k2) * 64;
        dst[e] = make_float4(p[jj], p[64 + jj], p[jj + 32], p[64 + jj + 32]);
    }
}

template<int R>
__device__ __forceinline__ void process_task(
    int b, int l0, float* sm, float* XA, float* XB, int lane,
    const int* __restrict__ nodes_v, const int* __restrict__ neigh_u,
    const int* __restrict__ neigh_r,
    const float* __restrict__ embed_u, const float* __restrict__ embed_i)
{
    const ulonglong2* W1Q = reinterpret_cast<const ulonglong2*>(sm + O_W1Q);
    const ulonglong2* W2Q = reinterpret_cast<const ulonglong2*>(sm + O_W2Q);
    const ulonglong2* W3Q = reinterpret_cast<const ulonglong2*>(sm + O_W3Q);
    const ulonglong2* A1Q = reinterpret_cast<const ulonglong2*>(sm + O_A1Q);
    const ulonglong2* A2Q = reinterpret_cast<const ulonglong2*>(sm + O_A2Q);

    int nrs[R];

    __syncwarp();
    // ---- gather x = embed_u[nu] into XA rows, read nr indices, q into XB row 0 ----
#pragma unroll
    for (int r = 0; r < R; r++) {
        int l  = l0 + r;
        int nu = neigh_u[b * LL + l];
        nrs[r] = neigh_r[b * LL + l];
        *reinterpret_cast<float2*>(&XA[r * 64 + 2 * lane]) =
            *reinterpret_cast<const float2*>(&embed_u[nu * 64 + 2 * lane]);
    }
    int iv = nodes_v[b];
    *reinterpret_cast<float2*>(&XB[2 * lane]) =
        *reinterpret_cast<const float2*>(&embed_i[iv * 64 + 2 * lane]);
    __syncwarp();

    // ---- qc: q-half of att layer 1 (same for all rows of this b) ----
    ull qA, qB;
    {
        ull a[1] = {0ULL}, c[1] = {0ULL};
        gemm_acc<1, 64, 64>(XB, A1Q + 1024, a, c, lane);
        qA = a[0]; qB = c[0];
    }
    __syncwarp();

    ull aA[R], aB[R];

    // ---- gv layer 1: pt-half (K=64) + er_proj[nr] init, relu -> XB ----
#pragma unroll
    for (int r = 0; r < R; r++) {
        const float* ep = sm + O_EP + nrs[r] * 64;
        aA[r] = pack2(ep[lane], 0.f);
        aB[r] = pack2(ep[lane + 32], 0.f);
    }
    gemm_acc<R, 64, 64>(XA, W1Q, aA, aB, lane);
    {
        float b0 = sm[O_BG1 + lane], b1 = sm[O_BG1 + lane + 32];
#pragma unroll
        for (int r = 0; r < R; r++) {
            float2 pa = unpack2(aA[r]), pb = unpack2(aB[r]);
            XB[r * 64 + lane]      = fmaxf(b0 + pa.x + pa.y, 0.f);
            XB[r * 64 + lane + 32] = fmaxf(b1 + pb.x + pb.y, 0.f);
        }
    }
    __syncwarp();

    // ---- gv layer 2: 64 -> 64, relu -> XA ----
#pragma unroll
    for (int r = 0; r < R; r++) { aA[r] = 0ULL; aB[r] = 0ULL; }
    gemm_acc<R, 64, 64>(XB, W2Q, aA, aB, lane);
    {
        float b0 = sm[O_BG2 + lane], b1 = sm[O_BG2 + lane + 32];
#pragma unroll
        for (int r = 0; r < R; r++) {
            float2 pa = unpack2(aA[r]), pb = unpack2(aB[r]);
            XA[r * 64 + lane]      = fmaxf(b0 + pa.x + pa.y, 0.f);
            XA[r * 64 + lane + 32] = fmaxf(b1 + pb.x + pb.y, 0.f);
        }
    }
    __syncwarp();

    // ---- gv layer 3: 64 -> 64 (no relu) = fjt -> XB and global ----
#pragma unroll
    for (int r = 0; r < R; r++) { aA[r] = 0ULL; aB[r] = 0ULL; }
    gemm_acc<R, 64, 64>(XA, W3Q, aA, aB, lane);
    {
        float b0 = sm[O_BG3 + lane], b1 = sm[O_BG3 + lane + 32];
#pragma unroll
        for (int r = 0; r < R; r++) {
            float2 pa = unpack2(aA[r]), pb = unpack2(aB[r]);
            float f0 = b0 + pa.x + pa.y;
            float f1 = b1 + pb.x + pb.y;
            XB[r * 64 + lane]      = f0;
            XB[r * 64 + lane + 32] = f1;
            int row = (b * LL + l0 + r) * 64;
            g_fjt[row + lane]      = f0;
            g_fjt[row + lane + 32] = f1;
        }
    }
    __syncwarp();

    // ---- att layer 1: fjt-half (K=64) + hoisted qc init, relu -> XA ----
#pragma unroll
    for (int r = 0; r < R; r++) { aA[r] = qA; aB[r] = qB; }
    gemm_acc<R, 64, 64>(XB, A1Q, aA, aB, lane);
    {
        float b0 = sm[O_BA1 + lane], b1 = sm[O_BA1 + lane + 32];
#pragma unroll
        for (int r = 0; r < R; r++) {
            float2 pa = unpack2(aA[r]), pb = unpack2(aB[r]);
            XA[r * 64 + lane]      = fmaxf(b0 + pa.x + pa.y, 0.f);
            XA[r * 64 + lane + 32] = fmaxf(b1 + pb.x + pb.y, 0.f);
        }
    }
    __syncwarp();

    // ---- att layer 2 + layer 3 (dot with w3) -> scores ----
#pragma unroll
    for (int r = 0; r < R; r++) { aA[r] = 0ULL; aB[r] = 0ULL; }
    gemm_acc<R, 64, 64>(XA, A2Q, aA, aB, lane);
    {
        float b0  = sm[O_BA2 + lane], b1 = sm[O_BA2 + lane + 32];
        float w3a = sm[O_W3V + lane], w3b = sm[O_W3V + lane + 32];
        float ba3 = sm[O_BA3];
#pragma unroll
        for (int r = 0; r < R; r++) {
            float2 pa = unpack2(aA[r]), pb = unpack2(aB[r]);
            float va = fmaxf(b0 + pa.x + pa.y, 0.f);
            float vb = fmaxf(b1 + pb.x + pb.y, 0.f);
            float p  = va * w3a + vb * w3b;
#pragma unroll
            for (int o = 16; o > 0; o >>= 1) p += __shfl_xor_sync(0xffffffffu, p, o);
            if (lane == 0) g_scores[b * LL + l0 + r] = p + ba3;
        }
    }
}

__global__ void __launch_bounds__(THREADS1, 1) mlp_kernel(
    const int* __restrict__ nodes_v, const int* __restrict__ neigh_u,
    const int* __restrict__ neigh_r,
    const float* __restrict__ embed_u, const float* __restrict__ embed_i,
    const float* __restrict__ embed_r,
    const float* __restrict__ gv_w1, const float* __restrict__ gv_b1,
    const float* __restrict__ gv_w2, const float* __restrict__ gv_b2,
    const float* __restrict__ gv_w3, const float* __restrict__ gv_b3,
    const float* __restrict__ att_w1, const float* __restrict__ att_b1,
    const float* __restrict__ att_w2, const float* __restrict__ att_b2,
    const float* __restrict__ att_w3, const float* __restrict__ att_b3)
{
    extern __shared__ float sm[];
    int tid = threadIdx.x;

    load_quads(sm + O_W1Q, gv_w1, 64, tid);     // pt half of gv_w1 (rows 0..63)
    load_quads(sm + O_W2Q, gv_w2, 64, tid);
    load_quads(sm + O_W3Q, gv_w3, 64, tid);
    load_quads(sm + O_A1Q, att_w1, 128, tid);   // full (lower=fjt half, upper=q half)
    load_quads(sm + O_A2Q, att_w2, 64, tid);
    if (tid < 64) {
        sm[O_W3V + tid] = att_w3[tid];
        sm[O_BG1 + tid] = gv_b1[tid];
        sm[O_BG2 + tid] = gv_b2[tid];
        sm[O_BG3 + tid] = gv_b3[tid];
        sm[O_BA1 + tid] = att_b1[tid];
        sm[O_BA2 + tid] = att_b2[tid];
    }
    if (tid == 0) sm[O_BA3] = att_b3[0];
    // er_proj[r][j] = sum_k embed_r[r][k] * gv_w1[64+k][j]   (NR=5, D=64)
    if (tid < 5 * 64) {
        int r = tid >> 6, j = tid & 63;
        float s = 0.f;
#pragma unroll 8
        for (int k = 0; k < 64; k++)
            s += embed_r[r * 64 + k] * gv_w1[(64 + k) * 64 + j];
        sm[O_EP + tid] = s;
    }
    __syncthreads();

    int lane = tid & 31, warp = tid >> 5;
    float* XA = sm + O_XA + warp * 8 * 64;
    float* XB = sm + O_XB + warp * 8 * 64;

    for (int t = blockIdx.x * NWARP + warp; t < NTASK; t += gridDim.x * NWARP) {
        int b = t / 7, q = t - b * 7;
        if (q < 6)
            process_task<8>(b, q * 8, sm, XA, XB, lane,
                            nodes_v, neigh_u, neigh_r, embed_u, embed_i);
        else
            process_task<2>(b, 48, sm, XA, XB, lane,
                            nodes_v, neigh_u, neigh_r, embed_u, embed_i);
    }
}

// ---- kernel 2: softmax over neighbors, aggregate, combine MLP ----
__global__ void __launch_bounds__(64) combine_kernel(
    const int* __restrict__ nodes_v, const float* __restrict__ embed_i,
    const float* __restrict__ wr1_w, const float* __restrict__ wr1_b,
    const float* __restrict__ wr2_w, const float* __restrict__ wr2_b,
    float* __restrict__ out)
{
    __shared__ float sc[64];
    __shared__ float es[64];
    __shared__ float mu[64];
    __shared__ float zq[128];
    __shared__ float zz[64];

    int b = blockIdx.x;
    int tid = threadIdx.x;

    sc[tid] = (tid < LL) ? g_scores[b * LL + tid] : -1e30f;
    __syncthreads();

    float mx = -1e30f;
#pragma unroll 10
    for (int l = 0; l < LL; l++) mx = fmaxf(mx, sc[l]);
    es[tid] = (tid < LL) ? __expf(sc[tid] - mx) : 0.f;
    __syncthreads();

    float den = 0.f;
#pragma unroll 10
    for (int l = 0; l < LL; l++) den += es[l];
    mu[tid] = es[tid] / den;
    __syncthreads();

    // zj[d] = sum_l mu[l] * fjt[b,l,d] ; zq = [zj, qj]
    float acc = 0.f;
    const float* fb = g_fjt + (size_t)(b * LL) * 64 + tid;
#pragma unroll 10
    for (int l = 0; l < LL; l++) acc += mu[l] * fb[l * 64];
    zq[tid] = acc;
    int iv = nodes_v[b];
    zq[64 + tid] = embed_i[iv * 64 + tid];
    __syncthreads();

    float a1 = wr1_b[tid];
#pragma unroll 8
    for (int k = 0; k < 128; k++) a1 += zq[k] * wr1_w[k * 64 + tid];
    zz[tid] = fmaxf(a1, 0.f);
    __syncthreads();

    float a2 = wr2_b[tid];
#pragma unroll 8
    for (int k = 0; k < 64; k++) a2 += zz[k] * wr2_w[k * 64 + tid];
    out[b * 64 + tid] = fmaxf(a2, 0.f);
}

extern "C" void kernel_launch(void* const* d_in, const int* in_sizes, int n_in,
                              void* d_out, int out_size)
{
    const int*   nodes_v = (const int*)d_in[0];
    const int*   neigh_u = (const int*)d_in[1];
    const int*   neigh_r = (const int*)d_in[2];
    const float* embed_u = (const float*)d_in[3];
    const float* embed_i = (const float*)d_in[4];
    const float* embed_r = (const float*)d_in[5];
    const float* gv_w1  = (const float*)d_in[6];
    const float* gv_b1  = (const float*)d_in[7];
    const float* gv_w2  = (const float*)d_in[8];
    const float* gv_b2  = (const float*)d_in[9];
    const float* gv_w3  = (const float*)d_in[10];
    const float* gv_b3  = (const float*)d_in[11];
    const float* att_w1 = (const float*)d_in[12];
    const float* att_b1 = (const float*)d_in[13];
    const float* att_w2 = (const float*)d_in[14];
    const float* att_b2 = (const float*)d_in[15];
    const float* att_w3 = (const float*)d_in[16];
    const float* att_b3 = (const float*)d_in[17];
    const float* wr1_w  = (const float*)d_in[18];
    const float* wr1_b  = (const float*)d_in[19];
    const float* wr2_w  = (const float*)d_in[20];
    const float* wr2_b  = (const float*)d_in[21];
    float* out = (float*)d_out;

    cudaFuncSetAttribute(mlp_kernel, cudaFuncAttributeMaxDynamicSharedMemorySize, SMEM_BYTES);

    int smCount = 148;
    cudaDeviceGetAttribute(&smCount, cudaDevAttrMultiProcessorCount, 0);

    mlp_kernel<<<smCount, THREADS1, SMEM_BYTES>>>(
        nodes_v, neigh_u, neigh_r, embed_u, embed_i, embed_r,
        gv_w1, gv_b1, gv_w2, gv_b2, gv_w3, gv_b3,
        att_w1, att_b1, att_w2, att_b2, att_w3, att_b3);

    combine_kernel<<<BB, 64>>>(nodes_v, embed_i, wr1_w, wr1_b, wr2_w, wr2_b, out);
}

// round 5
// speedup vs baseline: 2.2614x; 2.2614x over previous
#include <cuda_runtime.h>
#include <cuda_bf16.h>
#include <cstdint>
#include <math.h>

#define BB 4096
#define LL 50
#define DD 64

constexpr int ROWS_TOT = BB * LL;        // 204800
constexpr int NT16     = ROWS_TOT / 16;  // 12800 warp-tiles of 16 rows
constexpr int THR      = 256;            // 8 warps / block

// ---- smem byte layout ----
// Weights: 5 layers x (hi 8192 + lo 8192) in B-fragment order = 81920 B
constexpr int OFF_WS = 0;
constexpr int FBASE  = 81920;            // float region
constexpr int F_BG1 = 0, F_BG2 = 64, F_BG3 = 128, F_BA1 = 192, F_BA2 = 256;
constexpr int F_W3 = 320, F_BA3 = 384, F_ER = 448;   // er: 5*64
constexpr int SMEM_SZ = FBASE + (448 + 320) * 4;     // 84992 B

// device scratch
__device__ float g_scores[ROWS_TOT];
__device__ float g_fjt[ROWS_TOT * DD];
__device__ float g_qc[BB * DD];
__device__ float g_er[5 * DD];

// ===================== helpers =====================
// pack two fp32 -> bf16x2 (v_lo goes to low 16 bits = element 0)
__device__ __forceinline__ uint32_t cvt2(float v_lo, float v_hi) {
    uint32_t r;
    asm("cvt.rn.bf16x2.f32 %0, %1, %2;" : "=r"(r) : "f"(v_hi), "f"(v_lo));
    return r;
}
__device__ __forceinline__ float blo(uint32_t p) { return __uint_as_float(p << 16); }
__device__ __forceinline__ float bhi(uint32_t p) { return __uint_as_float(p & 0xffff0000u); }
__device__ __forceinline__ void split2(float v0, float v1, uint32_t& h, uint32_t& l) {
    h = cvt2(v0, v1);
    l = cvt2(v0 - blo(h), v1 - bhi(h));
}
__device__ __forceinline__ void mma(float* d, const uint32_t* a, uint32_t b0, uint32_t b1) {
    asm volatile(
        "mma.sync.aligned.m16n8k16.row.col.f32.bf16.bf16.f32 "
        "{%0,%1,%2,%3}, {%4,%5,%6,%7}, {%8,%9}, {%0,%1,%2,%3};"
        : "+f"(d[0]), "+f"(d[1]), "+f"(d[2]), "+f"(d[3])
        : "r"(a[0]), "r"(a[1]), "r"(a[2]), "r"(a[3]), "r"(b0), "r"(b1));
}

// One layer: D[16x64] = Ahi/Alo [16x64] @ W(hi/lo) [64x64], 3-pass split product.
__device__ __forceinline__ void run_layer(const char* ws, int lay,
        const uint32_t (&Ahi)[4][4], const uint32_t (&Alo)[4][4], float (&D)[8][4], int lane) {
#pragma unroll
    for (int nt = 0; nt < 8; nt++) { D[nt][0] = 0.f; D[nt][1] = 0.f; D[nt][2] = 0.f; D[nt][3] = 0.f; }
    const char* base = ws + lay * 16384 + lane * 8;
#pragma unroll
    for (int kt = 0; kt < 4; kt++) {
#pragma unroll
        for (int nt = 0; nt < 8; nt++) {
            const char* p = base + (kt * 8 + nt) * 256;
            uint2 bh = *reinterpret_cast<const uint2*>(p);
            uint2 bl = *reinterpret_cast<const uint2*>(p + 8192);
            mma(D[nt], Ahi[kt], bh.x, bh.y);
            mma(D[nt], Ahi[kt], bl.x, bl.y);
            mma(D[nt], Alo[kt], bh.x, bh.y);
        }
    }
}

// Epilogue: bias (+extra) (+relu) (+global store), then convert D-frags directly
// into next layer's A-frags (identical register layout) with hi/lo split.
template<bool RELU, bool EX, bool SG>
__device__ __forceinline__ void epilogue(float (&D)[8][4], uint32_t (&Ahi)[4][4], uint32_t (&Alo)[4][4],
        const float* bias, const float* e0, const float* e1, float* g0, float* g1, int tig) {
#pragma unroll
    for (int nt = 0; nt < 8; nt++) {
        int col = nt * 8 + 2 * tig;
        float2 bc = *reinterpret_cast<const float2*>(bias + col);
        float v0 = D[nt][0] + bc.x, v1 = D[nt][1] + bc.y;
        float v2 = D[nt][2] + bc.x, v3 = D[nt][3] + bc.y;
        if (EX) {
            float2 ea = *reinterpret_cast<const float2*>(e0 + col);
            float2 eb = *reinterpret_cast<const float2*>(e1 + col);
            v0 += ea.x; v1 += ea.y; v2 += eb.x; v3 += eb.y;
        }
        if (RELU) {
            v0 = fmaxf(v0, 0.f); v1 = fmaxf(v1, 0.f);
            v2 = fmaxf(v2, 0.f); v3 = fmaxf(v3, 0.f);
        }
        if (SG) {
            *reinterpret_cast<float2*>(g0 + col) = make_float2(v0, v1);
            *reinterpret_cast<float2*>(g1 + col) = make_float2(v2, v3);
        }
        int kt = nt >> 1, ix = (nt & 1) * 2;
        split2(v0, v1, Ahi[kt][ix],     Alo[kt][ix]);
        split2(v2, v3, Ahi[kt][ix + 1], Alo[kt][ix + 1]);
    }
}

// ===================== prep kernel: er_proj + qc =====================
__global__ void __launch_bounds__(64) prep_kernel(
    const int* __restrict__ nodes_v, const float* __restrict__ embed_i,
    const float* __restrict__ embed_r, const float* __restrict__ gv_w1,
    const float* __restrict__ att_w1) {
    int tid = threadIdx.x;
    if (blockIdx.x == 0) {
        for (int e = tid; e < 320; e += 64) {
            int r = e >> 6, j = e & 63;
            float s = 0.f;
#pragma unroll 8
            for (int k = 0; k < 64; k++) s += embed_r[r * 64 + k] * gv_w1[(64 + k) * 64 + j];
            g_er[e] = s;
        }
    } else {
        int b = blockIdx.x - 1;
        __shared__ float q[64];
        q[tid] = embed_i[(size_t)nodes_v[b] * 64 + tid];
        __syncthreads();
        float s = 0.f;
#pragma unroll 8
        for (int k = 0; k < 64; k++) s += q[k] * att_w1[(64 + k) * 64 + tid];
        g_qc[b * 64 + tid] = s;
    }
}

// ===================== HMMA MLP kernel =====================
__global__ void __launch_bounds__(THR, 2) mlp_mma_kernel(
    const int* __restrict__ neigh_u, const int* __restrict__ neigh_r,
    const float* __restrict__ embed_u,
    const float* __restrict__ gv_w1, const float* __restrict__ gv_b1,
    const float* __restrict__ gv_w2, const float* __restrict__ gv_b2,
    const float* __restrict__ gv_w3, const float* __restrict__ gv_b3,
    const float* __restrict__ att_w1, const float* __restrict__ att_b1,
    const float* __restrict__ att_w2, const float* __restrict__ att_b2,
    const float* __restrict__ att_w3, const float* __restrict__ att_b3) {
    extern __shared__ char smem[];
    float* smf = reinterpret_cast<float*>(smem + FBASE);
    int tid = threadIdx.x;

    // ---- prepack weights into B-fragment order (hi/lo bf16) ----
    {
        const float* srcs[5] = {gv_w1, gv_w2, gv_w3, att_w1, att_w2};
        for (int e = tid; e < 5 * 4 * 8 * 32; e += THR) {
            int lay = e >> 10;
            int rem = e & 1023;
            int kt = rem >> 8;
            int rem2 = rem & 255;
            int nt = rem2 >> 5;
            int th = rem2 & 31;
            int tg = th & 3, gn = th >> 2;
            int k0 = kt * 16 + tg * 2, n = nt * 8 + gn;
            const float* w = srcs[lay];
            uint32_t h0, l0, h1, l1;
            split2(w[k0 * 64 + n],       w[(k0 + 1) * 64 + n], h0, l0);
            split2(w[(k0 + 8) * 64 + n], w[(k0 + 9) * 64 + n], h1, l1);
            char* p = smem + OFF_WS + lay * 16384 + (kt * 8 + nt) * 256 + th * 8;
            *reinterpret_cast<uint2*>(p)        = make_uint2(h0, h1);
            *reinterpret_cast<uint2*>(p + 8192) = make_uint2(l0, l1);
        }
    }
    if (tid < 64) {
        smf[F_BG1 + tid] = gv_b1[tid];
        smf[F_BG2 + tid] = gv_b2[tid];
        smf[F_BG3 + tid] = gv_b3[tid];
        smf[F_BA1 + tid] = att_b1[tid];
        smf[F_BA2 + tid] = att_b2[tid];
        smf[F_W3 + tid]  = att_w3[tid];
    }
    for (int e = tid; e < 320; e += THR) smf[F_ER + e] = g_er[e];
    if (tid == 0) smf[F_BA3] = att_b3[0];
    __syncthreads();

    const char* ws = smem + OFF_WS;
    int lane = tid & 31;
    int tig = lane & 3, gid = lane >> 2;
    int gw = blockIdx.x * (THR / 32) + (tid >> 5);
    int stride = gridDim.x * (THR / 32);

    uint32_t Ahi[4][4], Alo[4][4];
    float D[8][4];

    for (int t = gw; t < NT16; t += stride) {
        int grow0 = t * 16 + gid, grow1 = grow0 + 8;
        int nu0 = neigh_u[grow0], nu1 = neigh_u[grow1];
        int nr0 = neigh_r[grow0], nr1 = neigh_r[grow1];
        int b0 = (int)((unsigned)grow0 / 50u), b1 = (int)((unsigned)grow1 / 50u);

        // ---- gather pt rows directly into A fragments (hi/lo split) ----
        const float* p0 = embed_u + (size_t)nu0 * 64 + 2 * tig;
        const float* p1 = embed_u + (size_t)nu1 * 64 + 2 * tig;
#pragma unroll
        for (int kt = 0; kt < 4; kt++) {
            float2 x0 = *reinterpret_cast<const float2*>(p0 + kt * 16);
            float2 x1 = *reinterpret_cast<const float2*>(p1 + kt * 16);
            float2 x2 = *reinterpret_cast<const float2*>(p0 + kt * 16 + 8);
            float2 x3 = *reinterpret_cast<const float2*>(p1 + kt * 16 + 8);
            split2(x0.x, x0.y, Ahi[kt][0], Alo[kt][0]);
            split2(x1.x, x1.y, Ahi[kt][1], Alo[kt][1]);
            split2(x2.x, x2.y, Ahi[kt][2], Alo[kt][2]);
            split2(x3.x, x3.y, Ahi[kt][3], Alo[kt][3]);
        }

        // L1: gv1(pt half) + er_proj[nr] + bg1, relu
        run_layer(ws, 0, Ahi, Alo, D, lane);
        epilogue<true, true, false>(D, Ahi, Alo, smf + F_BG1,
                                    smf + F_ER + nr0 * 64, smf + F_ER + nr1 * 64,
                                    nullptr, nullptr, tig);
        // L2: gv2 + bg2, relu
        run_layer(ws, 1, Ahi, Alo, D, lane);
        epilogue<true, false, false>(D, Ahi, Alo, smf + F_BG2,
                                     nullptr, nullptr, nullptr, nullptr, tig);
        // L3: gv3 + bg3 (no relu) -> fjt to gmem, also feeds att1
        run_layer(ws, 2, Ahi, Alo, D, lane);
        epilogue<false, false, true>(D, Ahi, Alo, smf + F_BG3,
                                     nullptr, nullptr,
                                     g_fjt + (size_t)grow0 * 64, g_fjt + (size_t)grow1 * 64, tig);
        // L4: att1(fjt half) + qc[b] + ba1, relu
        run_layer(ws, 3, Ahi, Alo, D, lane);
        epilogue<true, true, false>(D, Ahi, Alo, smf + F_BA1,
                                    g_qc + (size_t)b0 * 64, g_qc + (size_t)b1 * 64,
                                    nullptr, nullptr, tig);
        // L5: att2 + ba2, relu, dot w3 -> scores
        run_layer(ws, 4, Ahi, Alo, D, lane);
        {
            float s0 = 0.f, s1 = 0.f;
            float ba3v = smf[F_BA3];
#pragma unroll
            for (int nt = 0; nt < 8; nt++) {
                int col = nt * 8 + 2 * tig;
                float2 bc = *reinterpret_cast<const float2*>(smf + F_BA2 + col);
                float2 wc = *reinterpret_cast<const float2*>(smf + F_W3 + col);
                s0 += fmaxf(D[nt][0] + bc.x, 0.f) * wc.x + fmaxf(D[nt][1] + bc.y, 0.f) * wc.y;
                s1 += fmaxf(D[nt][2] + bc.x, 0.f) * wc.x + fmaxf(D[nt][3] + bc.y, 0.f) * wc.y;
            }
            s0 += __shfl_xor_sync(0xffffffffu, s0, 1);
            s0 += __shfl_xor_sync(0xffffffffu, s0, 2);
            s1 += __shfl_xor_sync(0xffffffffu, s1, 1);
            s1 += __shfl_xor_sync(0xffffffffu, s1, 2);
            if (tig == 0) {
                g_scores[grow0] = s0 + ba3v;
                g_scores[grow1] = s1 + ba3v;
            }
        }
    }
}

// ===================== combine kernel (known-good) =====================
__global__ void __launch_bounds__(64) combine_kernel(
    const int* __restrict__ nodes_v, const float* __restrict__ embed_i,
    const float* __restrict__ wr1_w, const float* __restrict__ wr1_b,
    const float* __restrict__ wr2_w, const float* __restrict__ wr2_b,
    float* __restrict__ out) {
    __shared__ float sc[64];
    __shared__ float es[64];
    __shared__ float mu[64];
    __shared__ float zq[128];
    __shared__ float zz[64];

    int b = blockIdx.x, tid = threadIdx.x;

    sc[tid] = (tid < LL) ? g_scores[b * LL + tid] : -1e30f;
    __syncthreads();

    float mx = -1e30f;
#pragma unroll 10
    for (int l = 0; l < LL; l++) mx = fmaxf(mx, sc[l]);
    es[tid] = (tid < LL) ? __expf(sc[tid] - mx) : 0.f;
    __syncthreads();

    float den = 0.f;
#pragma unroll 10
    for (int l = 0; l < LL; l++) den += es[l];
    mu[tid] = es[tid] / den;
    __syncthreads();

    float acc = 0.f;
    const float* fb = g_fjt + (size_t)(b * LL) * 64 + tid;
#pragma unroll 10
    for (int l = 0; l < LL; l++) acc += mu[l] * fb[l * 64];
    zq[tid] = acc;
    int iv = nodes_v[b];
    zq[64 + tid] = embed_i[iv * 64 + tid];
    __syncthreads();

    float a1 = wr1_b[tid];
#pragma unroll 8
    for (int k = 0; k < 128; k++) a1 += zq[k] * wr1_w[k * 64 + tid];
    zz[tid] = fmaxf(a1, 0.f);
    __syncthreads();

    float a2 = wr2_b[tid];
#pragma unroll 8
    for (int k = 0; k < 64; k++) a2 += zz[k] * wr2_w[k * 64 + tid];
    out[b * 64 + tid] = fmaxf(a2, 0.f);
}

extern "C" void kernel_launch(void* const* d_in, const int* in_sizes, int n_in,
                              void* d_out, int out_size) {
    const int*   nodes_v = (const int*)d_in[0];
    const int*   neigh_u = (const int*)d_in[1];
    const int*   neigh_r = (const int*)d_in[2];
    const float* embed_u = (const float*)d_in[3];
    const float* embed_i = (const float*)d_in[4];
    const float* embed_r = (const float*)d_in[5];
    const float* gv_w1  = (const float*)d_in[6];
    const float* gv_b1  = (const float*)d_in[7];
    const float* gv_w2  = (const float*)d_in[8];
    const float* gv_b2  = (const float*)d_in[9];
    const float* gv_w3  = (const float*)d_in[10];
    const float* gv_b3  = (const float*)d_in[11];
    const float* att_w1 = (const float*)d_in[12];
    const float* att_b1 = (const float*)d_in[13];
    const float* att_w2 = (const float*)d_in[14];
    const float* att_b2 = (const float*)d_in[15];
    const float* att_w3 = (const float*)d_in[16];
    const float* att_b3 = (const float*)d_in[17];
    const float* wr1_w  = (const float*)d_in[18];
    const float* wr1_b  = (const float*)d_in[19];
    const float* wr2_w  = (const float*)d_in[20];
    const float* wr2_b  = (const float*)d_in[21];
    float* out = (float*)d_out;

    cudaFuncSetAttribute(mlp_mma_kernel, cudaFuncAttributeMaxDynamicSharedMemorySize, SMEM_SZ);

    int smCount = 148;
    cudaDeviceGetAttribute(&smCount, cudaDevAttrMultiProcessorCount, 0);

    prep_kernel<<<BB + 1, 64>>>(nodes_v, embed_i, embed_r, gv_w1, att_w1);

    mlp_mma_kernel<<<2 * smCount, THR, SMEM_SZ>>>(
        neigh_u, neigh_r, embed_u,
        gv_w1, gv_b1, gv_w2, gv_b2, gv_w3, gv_b3,
        att_w1, att_b1, att_w2, att_b2, att_w3, att_b3);

    combine_kernel<<<BB, 64>>>(nodes_v, embed_i, wr1_w, wr1_b, wr2_w, wr2_b, out);
}